// round 1
// baseline (speedup 1.0000x reference)
#include <cuda_runtime.h>

#define NN 100000
#define EE 1600000
#define DIN 128
#define HIDD 64
#define GG 256
#define NLAYERS 3
#define BN_EPS 1e-5f

// ---------------- device scratch (no allocs allowed) ----------------
__device__ __align__(16) float g_deg[NN];
__device__ __align__(16) float g_dinv[NN];
__device__ __align__(16) int   g_src[EE];
__device__ __align__(16) int   g_dst[EE];
__device__ __align__(16) int   g_batch[NN];
__device__ __align__(16) float g_norm[EE];
__device__ __align__(16) float g_h[NN * HIDD];
__device__ __align__(16) float g_hw[NN * HIDD];
__device__ __align__(16) float g_agg[NN * HIDD];
__device__ __align__(16) float g_gsum[GG * HIDD];
__device__ __align__(16) float g_gcnt[GG];
__device__ int g_is64;

// ---------------- dtype detection: int64 vs int32 index arrays ----------------
// If edge_index is int64 (values < 2^31), every odd 32-bit word is zero.
__global__ void k_detect(const int* __restrict__ ei) {
    int nz = 0;
    for (int i = 0; i < 32; i++) nz |= ei[2 * i + 1];
    g_is64 = (nz == 0) ? 1 : 0;
}

// ---------------- init: zero agg/gsum/gcnt, deg=1 (self loop) ----------------
__global__ void k_init() {
    int i = blockIdx.x * blockDim.x + threadIdx.x;
    if (i < NN * HIDD) g_agg[i] = 0.f;
    if (i < NN) g_deg[i] = 1.f;
    if (i < GG * HIDD) g_gsum[i] = 0.f;
    if (i < GG) g_gcnt[i] = 0.f;
}

// ---------------- convert indices to int32 + degree count ----------------
__global__ void k_convert(const int* __restrict__ ei, const int* __restrict__ bt) {
    int i = blockIdx.x * blockDim.x + threadIdx.x;
    const bool is64 = (g_is64 != 0);
    if (i < EE) {
        int s = is64 ? ei[2 * i] : ei[i];
        int d = is64 ? ei[2 * (EE + i)] : ei[EE + i];
        g_src[i] = s;
        g_dst[i] = d;
        atomicAdd(&g_deg[d], 1.f);
    }
    if (i < NN) g_batch[i] = is64 ? bt[2 * i] : bt[i];
}

__global__ void k_dinv() {
    int i = blockIdx.x * blockDim.x + threadIdx.x;
    if (i < NN) g_dinv[i] = rsqrtf(g_deg[i]);   // deg >= 1 always
}

__global__ void k_norm() {
    int i = blockIdx.x * blockDim.x + threadIdx.x;
    if (i < EE) g_norm[i] = g_dinv[g_src[i]] * g_dinv[g_dst[i]];
}

// ---------------- tiled GEMM: C[N,64] = A[N,K] @ W[K,64] (+bias) ----------------
// 64-node tile per block, 256 threads as 16x16 groups, 4x4 micro-tile,
// K chunked by 32.  Inner loop: 2x LDS.128 + 16 FFMA per k.
template <int K>
__global__ void k_gemm(const float* __restrict__ A, const float* __restrict__ W,
                       const float* __restrict__ bias, float* __restrict__ C) {
    __shared__ float sA[32][68];   // [k][m], padded
    __shared__ float sW[32][68];   // [k][c], padded
    const int m0 = blockIdx.x * 64;
    const int tid = threadIdx.x;
    const int mg = tid / 16;   // 0..15 -> nodes mg*4 .. mg*4+3
    const int cg = tid % 16;   // 0..15 -> cols  cg*4 .. cg*4+3
    float acc[4][4];
#pragma unroll
    for (int i = 0; i < 4; i++)
#pragma unroll
        for (int j = 0; j < 4; j++) acc[i][j] = 0.f;

    for (int kb = 0; kb < K; kb += 32) {
        for (int t = tid; t < 64 * 32; t += 256) {
            int mm = t >> 5, kk = t & 31;
            int node = m0 + mm;
            sA[kk][mm] = (node < NN) ? A[(long)node * K + kb + kk] : 0.f;
        }
        for (int t = tid; t < 32 * 64; t += 256) {
            int kk = t >> 6, cc = t & 63;
            sW[kk][cc] = W[(kb + kk) * HIDD + cc];
        }
        __syncthreads();
#pragma unroll
        for (int kk = 0; kk < 32; kk++) {
            float4 a = *(const float4*)&sA[kk][mg * 4];
            float4 w = *(const float4*)&sW[kk][cg * 4];
            acc[0][0] += a.x * w.x; acc[0][1] += a.x * w.y; acc[0][2] += a.x * w.z; acc[0][3] += a.x * w.w;
            acc[1][0] += a.y * w.x; acc[1][1] += a.y * w.y; acc[1][2] += a.y * w.z; acc[1][3] += a.y * w.w;
            acc[2][0] += a.z * w.x; acc[2][1] += a.z * w.y; acc[2][2] += a.z * w.z; acc[2][3] += a.z * w.w;
            acc[3][0] += a.w * w.x; acc[3][1] += a.w * w.y; acc[3][2] += a.w * w.z; acc[3][3] += a.w * w.w;
        }
        __syncthreads();
    }
    float4 bv = make_float4(0.f, 0.f, 0.f, 0.f);
    if (bias) bv = *(const float4*)&bias[cg * 4];
#pragma unroll
    for (int i = 0; i < 4; i++) {
        int node = m0 + mg * 4 + i;
        if (node < NN) {
            float4 o;
            o.x = acc[i][0] + bv.x; o.y = acc[i][1] + bv.y;
            o.z = acc[i][2] + bv.z; o.w = acc[i][3] + bv.w;
            *(float4*)&C[(long)node * HIDD + cg * 4] = o;
        }
    }
}

// ---------------- edge scatter: agg[dst] += hw[src] * norm (float4 atomics) ----------------
__global__ void k_scatter() {
    long tid = (long)blockIdx.x * blockDim.x + threadIdx.x;
    if (tid >= (long)EE * 16) return;
    int e = (int)(tid >> 4);
    int q = (int)(tid & 15);
    int s = g_src[e];
    int d = g_dst[e];
    float w = g_norm[e];
    float4 v = *(const float4*)&g_hw[(long)s * HIDD + q * 4];
    v.x *= w; v.y *= w; v.z *= w; v.w *= w;
    atomicAdd((float4*)&g_agg[(long)d * HIDD + q * 4], v);
}

// ---------------- BN + ReLU + self-loop + bias; also re-zeroes agg ----------------
__global__ void k_bnrelu(const float* __restrict__ cb, const float* __restrict__ gamma,
                         const float* __restrict__ beta, const float* __restrict__ mean,
                         const float* __restrict__ var) {
    int i = blockIdx.x * blockDim.x + threadIdx.x;
    if (i >= NN * HIDD) return;
    int node = i >> 6;
    int c = i & 63;
    float di = g_dinv[node];
    float v = g_agg[i] + g_hw[i] * di * di + cb[c];
    g_agg[i] = 0.f;   // ready for next layer
    float hn = (v - mean[c]) * rsqrtf(var[c] + BN_EPS);
    hn = hn * gamma[c] + beta[c];
    g_h[i] = fmaxf(hn, 0.f);
}

// ---------------- per-graph mean pool (float4 atomics) ----------------
__global__ void k_pool() {
    int tid = blockIdx.x * blockDim.x + threadIdx.x;
    if (tid >= NN * 16) return;
    int i = tid >> 4;
    int q = tid & 15;
    int b = g_batch[i];
    float4 v = *(const float4*)&g_h[(long)i * HIDD + q * 4];
    atomicAdd((float4*)&g_gsum[b * HIDD + q * 4], v);
    if (q == 0) atomicAdd(&g_gcnt[b], 1.f);
}

// ---------------- MLP head: one block per graph ----------------
__global__ void k_mlp(const float* __restrict__ W1, const float* __restrict__ b1,
                      const float* __restrict__ W2, const float* __restrict__ b2,
                      const float* __restrict__ W3, const float* __restrict__ b3,
                      float* __restrict__ out) {
    __shared__ float v[64], a1[64], a2[32];
    int g = blockIdx.x;
    int c = threadIdx.x;
    float cnt = fmaxf(g_gcnt[g], 1.f);
    v[c] = g_gsum[g * HIDD + c] / cnt;
    __syncthreads();
    float s = b1[c];
#pragma unroll
    for (int k = 0; k < 64; k++) s += v[k] * W1[k * 64 + c];
    a1[c] = fmaxf(s, 0.f);
    __syncthreads();
    if (c < 32) {
        float s2 = b2[c];
#pragma unroll
        for (int k = 0; k < 64; k++) s2 += a1[k] * W2[k * 32 + c];
        a2[c] = fmaxf(s2, 0.f);
    }
    __syncthreads();
    if (c < 32) {
        float p = a2[c] * W3[c];
#pragma unroll
        for (int o = 16; o > 0; o >>= 1) p += __shfl_down_sync(0xffffffff, p, o);
        if (c == 0) out[g] = p + b3[0];
    }
}

// ---------------- launch ----------------
extern "C" void kernel_launch(void* const* d_in, const int* in_sizes, int n_in,
                              void* d_out, int out_size) {
    const float* x      = (const float*)d_in[0];
    const int*   ei     = (const int*)d_in[1];
    const int*   bt     = (const int*)d_in[2];
    const float* W_in   = (const float*)d_in[3];
    const float* b_in   = (const float*)d_in[4];
    const float* conv_W = (const float*)d_in[5];
    const float* conv_b = (const float*)d_in[6];
    const float* gamma  = (const float*)d_in[7];
    const float* beta   = (const float*)d_in[8];
    const float* mean   = (const float*)d_in[9];
    const float* var    = (const float*)d_in[10];
    const float* W1     = (const float*)d_in[11];
    const float* b1     = (const float*)d_in[12];
    const float* W2     = (const float*)d_in[13];
    const float* b2     = (const float*)d_in[14];
    const float* W3     = (const float*)d_in[15];
    const float* b3     = (const float*)d_in[16];
    float* out = (float*)d_out;

    float *p_h = nullptr, *p_hw = nullptr;
    cudaGetSymbolAddress((void**)&p_h, g_h);
    cudaGetSymbolAddress((void**)&p_hw, g_hw);

    k_detect<<<1, 1>>>(ei);
    k_init<<<(NN * HIDD + 255) / 256, 256>>>();
    k_convert<<<(EE + 255) / 256, 256>>>(ei, bt);
    k_dinv<<<(NN + 255) / 256, 256>>>();
    k_norm<<<(EE + 255) / 256, 256>>>();

    const int gemm_blocks = (NN + 63) / 64;
    k_gemm<DIN><<<gemm_blocks, 256>>>(x, W_in, b_in, p_h);

    const long scat_threads = (long)EE * 16;
    const int scat_blocks = (int)((scat_threads + 255) / 256);
    for (int l = 0; l < NLAYERS; l++) {
        k_gemm<HIDD><<<gemm_blocks, 256>>>(p_h, conv_W + (long)l * HIDD * HIDD, nullptr, p_hw);
        k_scatter<<<scat_blocks, 256>>>();
        k_bnrelu<<<(NN * HIDD + 255) / 256, 256>>>(conv_b + l * HIDD, gamma + l * HIDD,
                                                   beta + l * HIDD, mean + l * HIDD,
                                                   var + l * HIDD);
    }

    k_pool<<<(NN * 16 + 255) / 256, 256>>>();
    k_mlp<<<GG, 64>>>(W1, b1, W2, b2, W3, b3, out);
}

// round 2
// speedup vs baseline: 1.6932x; 1.6932x over previous
#include <cuda_runtime.h>

#define NN 100000
#define EE 1600000
#define DIN 128
#define HIDD 64
#define GG 256
#define NLAYERS 3
#define BN_EPS 1e-5f
#define NB_SCAN ((NN + 255) / 256)   // 391

// ---------------- device scratch (no allocs allowed) ----------------
__device__ __align__(16) int   g_cnt[NN];       // in-edge counts (excl. self loop)
__device__ __align__(16) int   g_fill[NN];      // CSR fill cursors
__device__ __align__(16) int   g_off[NN + 1];   // CSR row offsets
__device__ __align__(16) int   g_bsum[NB_SCAN];
__device__ __align__(16) int   g_boff[512];
__device__ __align__(16) float g_dinv[NN];
__device__ __align__(16) int   g_src[EE];
__device__ __align__(16) int   g_dst[EE];
__device__ __align__(16) int2  g_csr[EE];       // .x = src, .y = bits(norm)
__device__ __align__(16) int   g_batch[NN];
__device__ __align__(16) float g_h[NN * HIDD];  // node features
__device__ __align__(16) float g_a[NN * HIDD];  // aggregated features
__device__ __align__(16) float g_gsum[GG * HIDD];
__device__ __align__(16) float g_gcnt[GG];
__device__ int g_is64;

// ---------------- dtype detection: int64 vs int32 index arrays ----------------
__global__ void k_detect(const int* __restrict__ ei) {
    int nz = 0;
    for (int i = 0; i < 32; i++) nz |= ei[2 * i + 1];
    g_is64 = (nz == 0) ? 1 : 0;
}

// ---------------- init: zero counters ----------------
__global__ void k_init() {
    int i = blockIdx.x * blockDim.x + threadIdx.x;
    if (i < NN) { g_cnt[i] = 0; g_fill[i] = 0; }
    if (i < GG * HIDD) g_gsum[i] = 0.f;
    if (i < GG) g_gcnt[i] = 0.f;
    if (i == 0) g_off[NN] = EE;
}

// ---------------- convert indices to int32 + in-degree count ----------------
__global__ void k_convert(const int* __restrict__ ei, const int* __restrict__ bt) {
    int i = blockIdx.x * blockDim.x + threadIdx.x;
    const bool is64 = (g_is64 != 0);
    if (i < EE) {
        int s = is64 ? ei[2 * i] : ei[i];
        int d = is64 ? ei[2 * (EE + i)] : ei[EE + i];
        g_src[i] = s;
        g_dst[i] = d;
        atomicAdd(&g_cnt[d], 1);
    }
    if (i < NN) g_batch[i] = is64 ? bt[2 * i] : bt[i];
}

__global__ void k_dinv() {
    int i = blockIdx.x * blockDim.x + threadIdx.x;
    if (i < NN) g_dinv[i] = rsqrtf((float)(g_cnt[i] + 1));  // +1 self loop
}

// ---------------- prefix scan of counts -> CSR offsets ----------------
__global__ void k_scan_block() {   // grid = NB_SCAN, block = 256
    __shared__ int s[256];
    int b = blockIdx.x, t = threadIdx.x, i = b * 256 + t;
    int v = (i < NN) ? g_cnt[i] : 0;
    s[t] = v; __syncthreads();
#pragma unroll
    for (int o = 1; o < 256; o <<= 1) {
        int x = (t >= o) ? s[t - o] : 0;
        __syncthreads();
        s[t] += x;
        __syncthreads();
    }
    if (i < NN) g_off[i] = s[t] - v;      // exclusive
    if (t == 255) g_bsum[b] = s[255];
}

__global__ void k_scan_top() {     // 1 block, 512 threads
    __shared__ int s[512];
    int t = threadIdx.x;
    int v = (t < NB_SCAN) ? g_bsum[t] : 0;
    s[t] = v; __syncthreads();
#pragma unroll
    for (int o = 1; o < 512; o <<= 1) {
        int x = (t >= o) ? s[t - o] : 0;
        __syncthreads();
        s[t] += x;
        __syncthreads();
    }
    g_boff[t] = s[t] - v;                 // exclusive
}

__global__ void k_scan_add() {
    int i = blockIdx.x * blockDim.x + threadIdx.x;
    if (i < NN) g_off[i] += g_boff[i >> 8];
}

// ---------------- place edges into CSR (dst-grouped), norm computed inline ----
__global__ void k_place() {
    int e = blockIdx.x * blockDim.x + threadIdx.x;
    if (e >= EE) return;
    int s = g_src[e], d = g_dst[e];
    float w = g_dinv[s] * g_dinv[d];
    int pos = g_off[d] + atomicAdd(&g_fill[d], 1);
    g_csr[pos] = make_int2(s, __float_as_int(w));
}

// ---------------- gather: a[i] = sum_{e: dst=i} norm*h[src] + dinv^2*h[i] ----
__global__ void k_gather(const float* __restrict__ h, float* __restrict__ a) {
    int gw = (blockIdx.x * blockDim.x + threadIdx.x) >> 5;
    int lane = threadIdx.x & 31;
    if (gw >= NN) return;
    float di = g_dinv[gw];
    float sw = di * di;
    const float2* hrow = (const float2*)&h[(long)gw * HIDD];
    float2 acc = hrow[lane];
    acc.x *= sw; acc.y *= sw;
    int e = g_off[gw], end = g_off[gw + 1];
    for (; e + 1 < end; e += 2) {
        int2 m0 = g_csr[e];
        int2 m1 = g_csr[e + 1];
        float w0 = __int_as_float(m0.y), w1 = __int_as_float(m1.y);
        float2 v0 = *(const float2*)&h[(long)m0.x * HIDD + lane * 2];
        float2 v1 = *(const float2*)&h[(long)m1.x * HIDD + lane * 2];
        acc.x += w0 * v0.x + w1 * v1.x;
        acc.y += w0 * v0.y + w1 * v1.y;
    }
    if (e < end) {
        int2 m = g_csr[e];
        float w = __int_as_float(m.y);
        float2 v = *(const float2*)&h[(long)m.x * HIDD + lane * 2];
        acc.x += w * v.x;
        acc.y += w * v.y;
    }
    *(float2*)&a[(long)gw * HIDD + lane * 2] = acc;
}

// ---------------- tiled GEMM: C[N,64] = A[N,K] @ W[K,64] + epilogue ----------
// FUSE=0: +bias only.  FUSE=1: +bias, BN(eval), ReLU.
template <int K, int FUSE>
__global__ void k_gemm(const float* __restrict__ A, const float* __restrict__ W,
                       const float* __restrict__ bias,
                       const float* __restrict__ gamma, const float* __restrict__ beta,
                       const float* __restrict__ mean, const float* __restrict__ var,
                       float* __restrict__ C) {
    __shared__ float sA[32][68];   // [k][m], padded
    __shared__ float sW[32][68];   // [k][c], padded
    const int m0 = blockIdx.x * 64;
    const int tid = threadIdx.x;
    const int mg = tid / 16;
    const int cg = tid % 16;
    float acc[4][4];
#pragma unroll
    for (int i = 0; i < 4; i++)
#pragma unroll
        for (int j = 0; j < 4; j++) acc[i][j] = 0.f;

    for (int kb = 0; kb < K; kb += 32) {
        for (int t = tid; t < 64 * 32; t += 256) {
            int mm = t >> 5, kk = t & 31;
            int node = m0 + mm;
            sA[kk][mm] = (node < NN) ? A[(long)node * K + kb + kk] : 0.f;
        }
        for (int t = tid; t < 32 * 64; t += 256) {
            int kk = t >> 6, cc = t & 63;
            sW[kk][cc] = W[(kb + kk) * HIDD + cc];
        }
        __syncthreads();
#pragma unroll
        for (int kk = 0; kk < 32; kk++) {
            float4 aa = *(const float4*)&sA[kk][mg * 4];
            float4 ww = *(const float4*)&sW[kk][cg * 4];
            acc[0][0] += aa.x * ww.x; acc[0][1] += aa.x * ww.y; acc[0][2] += aa.x * ww.z; acc[0][3] += aa.x * ww.w;
            acc[1][0] += aa.y * ww.x; acc[1][1] += aa.y * ww.y; acc[1][2] += aa.y * ww.z; acc[1][3] += aa.y * ww.w;
            acc[2][0] += aa.z * ww.x; acc[2][1] += aa.z * ww.y; acc[2][2] += aa.z * ww.z; acc[2][3] += aa.z * ww.w;
            acc[3][0] += aa.w * ww.x; acc[3][1] += aa.w * ww.y; acc[3][2] += aa.w * ww.z; acc[3][3] += aa.w * ww.w;
        }
        __syncthreads();
    }
    // epilogue params for this thread's 4 columns
    float4 bv = *(const float4*)&bias[cg * 4];
    float sc[4], sh[4];
    if (FUSE) {
        float4 gm = *(const float4*)&gamma[cg * 4];
        float4 be = *(const float4*)&beta[cg * 4];
        float4 mn = *(const float4*)&mean[cg * 4];
        float4 vr = *(const float4*)&var[cg * 4];
        sc[0] = gm.x * rsqrtf(vr.x + BN_EPS); sh[0] = be.x - mn.x * sc[0];
        sc[1] = gm.y * rsqrtf(vr.y + BN_EPS); sh[1] = be.y - mn.y * sc[1];
        sc[2] = gm.z * rsqrtf(vr.z + BN_EPS); sh[2] = be.z - mn.z * sc[2];
        sc[3] = gm.w * rsqrtf(vr.w + BN_EPS); sh[3] = be.w - mn.w * sc[3];
    }
#pragma unroll
    for (int i = 0; i < 4; i++) {
        int node = m0 + mg * 4 + i;
        if (node < NN) {
            float o[4] = {acc[i][0] + bv.x, acc[i][1] + bv.y,
                          acc[i][2] + bv.z, acc[i][3] + bv.w};
            if (FUSE) {
#pragma unroll
                for (int j = 0; j < 4; j++) o[j] = fmaxf(o[j] * sc[j] + sh[j], 0.f);
            }
            *(float4*)&C[(long)node * HIDD + cg * 4] = make_float4(o[0], o[1], o[2], o[3]);
        }
    }
}

// ---------------- per-graph mean pool (float4 atomics) ----------------
__global__ void k_pool() {
    int tid = blockIdx.x * blockDim.x + threadIdx.x;
    if (tid >= NN * 16) return;
    int i = tid >> 4;
    int q = tid & 15;
    int b = g_batch[i];
    float4 v = *(const float4*)&g_h[(long)i * HIDD + q * 4];
    atomicAdd((float4*)&g_gsum[b * HIDD + q * 4], v);
    if (q == 0) atomicAdd(&g_gcnt[b], 1.f);
}

// ---------------- MLP head: one block per graph ----------------
__global__ void k_mlp(const float* __restrict__ W1, const float* __restrict__ b1,
                      const float* __restrict__ W2, const float* __restrict__ b2,
                      const float* __restrict__ W3, const float* __restrict__ b3,
                      float* __restrict__ out) {
    __shared__ float v[64], a1[64], a2[32];
    int g = blockIdx.x;
    int c = threadIdx.x;
    float cnt = fmaxf(g_gcnt[g], 1.f);
    v[c] = g_gsum[g * HIDD + c] / cnt;
    __syncthreads();
    float s = b1[c];
#pragma unroll
    for (int k = 0; k < 64; k++) s += v[k] * W1[k * 64 + c];
    a1[c] = fmaxf(s, 0.f);
    __syncthreads();
    if (c < 32) {
        float s2 = b2[c];
#pragma unroll
        for (int k = 0; k < 64; k++) s2 += a1[k] * W2[k * 32 + c];
        a2[c] = fmaxf(s2, 0.f);
    }
    __syncthreads();
    if (c < 32) {
        float p = a2[c] * W3[c];
#pragma unroll
        for (int o = 16; o > 0; o >>= 1) p += __shfl_down_sync(0xffffffff, p, o);
        if (c == 0) out[g] = p + b3[0];
    }
}

// ---------------- launch ----------------
extern "C" void kernel_launch(void* const* d_in, const int* in_sizes, int n_in,
                              void* d_out, int out_size) {
    const float* x      = (const float*)d_in[0];
    const int*   ei     = (const int*)d_in[1];
    const int*   bt     = (const int*)d_in[2];
    const float* W_in   = (const float*)d_in[3];
    const float* b_in   = (const float*)d_in[4];
    const float* conv_W = (const float*)d_in[5];
    const float* conv_b = (const float*)d_in[6];
    const float* gamma  = (const float*)d_in[7];
    const float* beta   = (const float*)d_in[8];
    const float* mean   = (const float*)d_in[9];
    const float* var    = (const float*)d_in[10];
    const float* W1     = (const float*)d_in[11];
    const float* b1     = (const float*)d_in[12];
    const float* W2     = (const float*)d_in[13];
    const float* b2     = (const float*)d_in[14];
    const float* W3     = (const float*)d_in[15];
    const float* b3     = (const float*)d_in[16];
    float* out = (float*)d_out;

    float *p_h = nullptr, *p_a = nullptr;
    cudaGetSymbolAddress((void**)&p_h, g_h);
    cudaGetSymbolAddress((void**)&p_a, g_a);

    k_detect<<<1, 1>>>(ei);
    k_init<<<(NN + 255) / 256, 256>>>();
    k_convert<<<(EE + 255) / 256, 256>>>(ei, bt);
    k_dinv<<<(NN + 255) / 256, 256>>>();
    k_scan_block<<<NB_SCAN, 256>>>();
    k_scan_top<<<1, 512>>>();
    k_scan_add<<<(NN + 255) / 256, 256>>>();
    k_place<<<(EE + 255) / 256, 256>>>();

    const int gemm_blocks = (NN + 63) / 64;
    // h0 = x @ W_in + b_in
    k_gemm<DIN, 0><<<gemm_blocks, 256>>>(x, W_in, b_in,
                                         nullptr, nullptr, nullptr, nullptr, p_h);

    const int gather_blocks = (NN * 32 + 255) / 256;
    for (int l = 0; l < NLAYERS; l++) {
        k_gather<<<gather_blocks, 256>>>(p_h, p_a);      // a = Agg(h)
        k_gemm<HIDD, 1><<<gemm_blocks, 256>>>(p_a, conv_W + (long)l * HIDD * HIDD,
                                              conv_b + l * HIDD,
                                              gamma + l * HIDD, beta + l * HIDD,
                                              mean + l * HIDD, var + l * HIDD, p_h);
    }

    k_pool<<<(NN * 16 + 255) / 256, 256>>>();
    k_mlp<<<GG, 64>>>(W1, b1, W2, b2, W3, b3, out);
}